// round 2
// baseline (speedup 1.0000x reference)
#include <cuda_runtime.h>

#define NN 50000
#define DIMX 128
#define NE 800000

// ---- scratch (static __device__ globals; no runtime allocation) ----
__device__ float g_hbuf[2][NN * DIMX];   // ping-pong hidden states
__device__ float g_agg[NN * DIMX];       // aggregation buffer
__device__ int   g_off[NN + 1];          // CSR row offsets (by dst)
__device__ int   g_cnt[NN];              // degree / fill counters
__device__ int   g_srt[NE];              // CSR column indices (src sorted by dst)
__device__ float g_ro[DIMX];             // readout vector (sum over nodes)
__device__ float g_bias[DIMX];           // combined per-layer bias (Vb+Ab+Rb+ro@Rw^T)
__device__ float g_WT[2 * DIMX * DIMX];  // transposed weights: [phase][k][j]

// ---------------- setup kernels ----------------

__global__ void copy_x_kernel(const float* __restrict__ x, int n4) {
    int i = blockIdx.x * blockDim.x + threadIdx.x;
    if (i < n4) {
        reinterpret_cast<float4*>(g_hbuf[0])[i] =
            reinterpret_cast<const float4*>(x)[i];
    }
}

__global__ void zero_cnt_kernel(int n) {
    int i = blockIdx.x * blockDim.x + threadIdx.x;
    if (i < n) g_cnt[i] = 0;
}

__global__ void hist_kernel(const int* __restrict__ dst, int e) {
    int i = blockIdx.x * blockDim.x + threadIdx.x;
    if (i < e) atomicAdd(&g_cnt[dst[i]], 1);
}

// single-block exclusive scan of g_cnt -> g_off; zeroes g_cnt for reuse
__global__ void scan_kernel(int n) {
    __shared__ int s[1024];
    __shared__ int carry;
    if (threadIdx.x == 0) carry = 0;
    __syncthreads();
    for (int base = 0; base < n; base += 1024) {
        int i = base + threadIdx.x;
        int v = (i < n) ? g_cnt[i] : 0;
        s[threadIdx.x] = v;
        __syncthreads();
        for (int off = 1; off < 1024; off <<= 1) {
            int t = (threadIdx.x >= off) ? s[threadIdx.x - off] : 0;
            __syncthreads();
            s[threadIdx.x] += t;
            __syncthreads();
        }
        int incl = s[threadIdx.x];
        if (i < n) {
            g_off[i] = carry + incl - v;
            g_cnt[i] = 0;
        }
        __syncthreads();
        if (threadIdx.x == 1023) carry += s[1023];
        __syncthreads();
    }
    if (threadIdx.x == 0) g_off[n] = carry;
}

__global__ void scatter_kernel(const int* __restrict__ src,
                               const int* __restrict__ dst, int e) {
    int i = blockIdx.x * blockDim.x + threadIdx.x;
    if (i < e) {
        int d = dst[i];
        int pos = g_off[d] + atomicAdd(&g_cnt[d], 1);
        g_srt[pos] = src[i];
    }
}

// ---------------- per-layer kernels ----------------

__global__ void zero_ro_kernel() { g_ro[threadIdx.x] = 0.0f; }

__global__ void readout_kernel(int insel, int n) {
    const float* __restrict__ h = g_hbuf[insel];
    int j = threadIdx.x;  // 128 threads
    float s = 0.0f;
    for (int i = blockIdx.x; i < n; i += gridDim.x) s += h[i * DIMX + j];
    atomicAdd(&g_ro[j], s);
}

__global__ void bias_kernel(const float* __restrict__ Vb,
                            const float* __restrict__ Ab,
                            const float* __restrict__ Rb,
                            const float* __restrict__ Rw, int l) {
    int j = threadIdx.x;  // 128 threads
    const float* r = Rw + (size_t)l * DIMX * DIMX + (size_t)j * DIMX;
    float acc = 0.0f;
#pragma unroll 4
    for (int k = 0; k < DIMX; k++) acc += g_ro[k] * r[k];
    g_bias[j] = Vb[l * DIMX + j] + Ab[l * DIMX + j] + Rb[l * DIMX + j] + acc;
}

__global__ void wtrans_kernel(const float* __restrict__ Vw,
                              const float* __restrict__ Aw, int l) {
    int idx = blockIdx.x * blockDim.x + threadIdx.x;  // 2*128*128 total
    if (idx >= 2 * DIMX * DIMX) return;
    int phase = idx / (DIMX * DIMX);
    int rem = idx - phase * DIMX * DIMX;
    int k = rem >> 7;
    int j = rem & 127;
    const float* W = phase ? Aw : Vw;
    g_WT[idx] = W[(size_t)l * DIMX * DIMX + (size_t)j * DIMX + k];
}

// agg[i] = h[i] + sum_{e in csr(i)} h[srt[e]]
__global__ void agg_kernel(int insel, int n) {
    const float* __restrict__ h = g_hbuf[insel];
    int i = blockIdx.x;
    int j = threadIdx.x;  // 128 threads, one per dim
    int beg = g_off[i], end = g_off[i + 1];
    float s = h[i * DIMX + j];
    int e = beg;
    for (; e + 4 <= end; e += 4) {
        int s0 = g_srt[e + 0];
        int s1 = g_srt[e + 1];
        int s2 = g_srt[e + 2];
        int s3 = g_srt[e + 3];
        s += h[s0 * DIMX + j];
        s += h[s1 * DIMX + j];
        s += h[s2 * DIMX + j];
        s += h[s3 * DIMX + j];
    }
    for (; e < end; ++e) s += h[g_srt[e] * DIMX + j];
    g_agg[i * DIMX + j] = s;
}

// h_out = relu( h @ Vw^T + agg @ Aw^T + g_bias )
// tiled SGEMM: BM=128, BN=128 (full), BK=16, 256 threads, 8x8 micro-tile
__global__ void __launch_bounds__(256, 2)
gemm_relu_kernel(int insel, int outsel, int n) {
    __shared__ float As[16][132];
    __shared__ float Bs[16][128];
    const int tid = threadIdx.x;
    const int tx = tid & 15;
    const int ty = tid >> 4;
    const int bm = blockIdx.x * 128;

    float acc[8][8];
#pragma unroll
    for (int r = 0; r < 8; r++)
#pragma unroll
        for (int c = 0; c < 8; c++) acc[r][c] = 0.0f;

#pragma unroll
    for (int phase = 0; phase < 2; ++phase) {
        const float* __restrict__ A = phase ? g_agg : g_hbuf[insel];
        const float* __restrict__ W = g_WT + phase * DIMX * DIMX;
        for (int kk = 0; kk < DIMX; kk += 16) {
            // A tile 128x16 via float4 (2 per thread)
#pragma unroll
            for (int i = 0; i < 2; i++) {
                int idx4 = tid + i * 256;
                int m = idx4 >> 2;
                int k4 = (idx4 & 3) << 2;
                int gm = bm + m;
                float4 v = make_float4(0.f, 0.f, 0.f, 0.f);
                if (gm < n)
                    v = *reinterpret_cast<const float4*>(&A[gm * DIMX + kk + k4]);
                As[k4 + 0][m] = v.x;
                As[k4 + 1][m] = v.y;
                As[k4 + 2][m] = v.z;
                As[k4 + 3][m] = v.w;
            }
            // B tile 16x128 via float4 (2 per thread)
#pragma unroll
            for (int i = 0; i < 2; i++) {
                int idx4 = tid + i * 256;
                int k = idx4 >> 5;
                int n4 = (idx4 & 31) << 2;
                *reinterpret_cast<float4*>(&Bs[k][n4]) =
                    *reinterpret_cast<const float4*>(&W[(kk + k) * DIMX + n4]);
            }
            __syncthreads();
#pragma unroll
            for (int k = 0; k < 16; k++) {
                float4 a0 = *reinterpret_cast<const float4*>(&As[k][ty * 8]);
                float4 a1 = *reinterpret_cast<const float4*>(&As[k][ty * 8 + 4]);
                float4 b0 = *reinterpret_cast<const float4*>(&Bs[k][tx * 8]);
                float4 b1 = *reinterpret_cast<const float4*>(&Bs[k][tx * 8 + 4]);
                float a[8] = {a0.x, a0.y, a0.z, a0.w, a1.x, a1.y, a1.z, a1.w};
                float b[8] = {b0.x, b0.y, b0.z, b0.w, b1.x, b1.y, b1.z, b1.w};
#pragma unroll
                for (int r = 0; r < 8; r++)
#pragma unroll
                    for (int c = 0; c < 8; c++) acc[r][c] += a[r] * b[c];
            }
            __syncthreads();
        }
    }

    float* __restrict__ O = g_hbuf[outsel];
#pragma unroll
    for (int r = 0; r < 8; r++) {
        int gm = bm + ty * 8 + r;
        if (gm < n) {
            int j0 = tx * 8;
            float4 o0, o1;
            o0.x = fmaxf(acc[r][0] + g_bias[j0 + 0], 0.f);
            o0.y = fmaxf(acc[r][1] + g_bias[j0 + 1], 0.f);
            o0.z = fmaxf(acc[r][2] + g_bias[j0 + 2], 0.f);
            o0.w = fmaxf(acc[r][3] + g_bias[j0 + 3], 0.f);
            o1.x = fmaxf(acc[r][4] + g_bias[j0 + 4], 0.f);
            o1.y = fmaxf(acc[r][5] + g_bias[j0 + 5], 0.f);
            o1.z = fmaxf(acc[r][6] + g_bias[j0 + 6], 0.f);
            o1.w = fmaxf(acc[r][7] + g_bias[j0 + 7], 0.f);
            *reinterpret_cast<float4*>(&O[gm * DIMX + j0]) = o0;
            *reinterpret_cast<float4*>(&O[gm * DIMX + j0 + 4]) = o1;
        }
    }
}

// out[i][o] = sigmoid(h[i] . out_w[o] + out_b[o]), o in {0,1}; warp per node
__global__ void out_kernel(int insel, const float* __restrict__ ow,
                           const float* __restrict__ ob,
                           float* __restrict__ out, int n) {
    const float* __restrict__ h = g_hbuf[insel];
    int gw = (blockIdx.x * blockDim.x + threadIdx.x) >> 5;
    int lane = threadIdx.x & 31;
    if (gw >= n) return;
    const float* hr = h + (size_t)gw * DIMX;
    float a0 = 0.f, a1 = 0.f;
#pragma unroll
    for (int k = lane; k < DIMX; k += 32) {
        float v = hr[k];
        a0 += v * ow[k];
        a1 += v * ow[DIMX + k];
    }
#pragma unroll
    for (int o = 16; o; o >>= 1) {
        a0 += __shfl_down_sync(0xffffffffu, a0, o);
        a1 += __shfl_down_sync(0xffffffffu, a1, o);
    }
    if (lane == 0) {
        out[gw * 2 + 0] = 1.0f / (1.0f + __expf(-(a0 + ob[0])));
        out[gw * 2 + 1] = 1.0f / (1.0f + __expf(-(a1 + ob[1])));
    }
}

// ---------------- launch ----------------

extern "C" void kernel_launch(void* const* d_in, const int* in_sizes, int n_in,
                              void* d_out, int out_size) {
    const float* x  = (const float*)d_in[0];
    const int* src  = (const int*)d_in[1];
    const int* dst  = (const int*)d_in[2];
    const float* Vw = (const float*)d_in[3];
    const float* Vb = (const float*)d_in[4];
    const float* Aw = (const float*)d_in[5];
    const float* Ab = (const float*)d_in[6];
    const float* Rw = (const float*)d_in[7];
    const float* Rb = (const float*)d_in[8];
    const float* ow = (const float*)d_in[9];
    const float* ob = (const float*)d_in[10];
    float* out = (float*)d_out;

    const int n = in_sizes[0] / DIMX;   // 50000
    const int e = in_sizes[1];          // 800000

    // stage input into ping-pong buffer 0
    int n4 = (n * DIMX) / 4;
    copy_x_kernel<<<(n4 + 255) / 256, 256>>>(x, n4);

    // build CSR by dst
    zero_cnt_kernel<<<(n + 255) / 256, 256>>>(n);
    hist_kernel<<<(e + 255) / 256, 256>>>(dst, e);
    scan_kernel<<<1, 1024>>>(n);
    scatter_kernel<<<(e + 255) / 256, 256>>>(src, dst, e);

    for (int l = 0; l < 3; l++) {
        int insel = l & 1;       // 0,1,0
        int outsel = insel ^ 1;  // 1,0,1
        zero_ro_kernel<<<1, 128>>>();
        readout_kernel<<<512, 128>>>(insel, n);
        bias_kernel<<<1, 128>>>(Vb, Ab, Rb, Rw, l);
        wtrans_kernel<<<128, 256>>>(Vw, Aw, l);
        agg_kernel<<<n, 128>>>(insel, n);
        gemm_relu_kernel<<<(n + 127) / 128, 256>>>(insel, outsel, n);
    }

    // final hidden state is in g_hbuf[1] (layer 2: insel=0 -> outsel=1)
    out_kernel<<<(n + 7) / 8, 256>>>(1, ow, ob, out, n);
}

// round 4
// speedup vs baseline: 2.0831x; 2.0831x over previous
#include <cuda_runtime.h>
#include <cuda_bf16.h>
#include <cstdint>

#define NN 50000
#define DIMX 128
#define NE 800000

// ---- scratch (static __device__ globals; no runtime allocation) ----
__device__ __nv_bfloat16 g_hb16[2][NN * DIMX];   // ping-pong hidden states (bf16)
__device__ __nv_bfloat16 g_aggb16[NN * DIMX];    // aggregation (bf16)
__device__ __nv_bfloat16 g_Wb16[3 * 2 * DIMX * DIMX]; // [layer][phase V/A][n][k] bf16
__device__ int   g_off[NN + 1];
__device__ int   g_cnt[NN];
__device__ int   g_srt[NE];
__device__ int   g_bsum[64];
__device__ float g_ro[DIMX];
__device__ float g_bias[DIMX];

// ================= helpers =================

__device__ __forceinline__ uint32_t smem_u32(const void* p) {
    uint32_t a;
    asm("{ .reg .u64 t; cvta.to.shared.u64 t, %1; cvt.u32.u64 %0, t; }"
        : "=r"(a) : "l"(p));
    return a;
}

__device__ __forceinline__ void ldm_x4(uint32_t* r, uint32_t addr) {
    asm volatile("ldmatrix.sync.aligned.m8n8.x4.shared.b16 {%0,%1,%2,%3}, [%4];"
                 : "=r"(r[0]), "=r"(r[1]), "=r"(r[2]), "=r"(r[3]) : "r"(addr));
}

__device__ __forceinline__ void mma_bf16(float* c, const uint32_t* a,
                                         const uint32_t* b) {
    asm volatile(
        "mma.sync.aligned.m16n8k16.row.col.f32.bf16.bf16.f32 "
        "{%0,%1,%2,%3}, {%4,%5,%6,%7}, {%8,%9}, {%0,%1,%2,%3};"
        : "+f"(c[0]), "+f"(c[1]), "+f"(c[2]), "+f"(c[3])
        : "r"(a[0]), "r"(a[1]), "r"(a[2]), "r"(a[3]), "r"(b[0]), "r"(b[1]));
}

// ================= setup kernels =================

__global__ void copy_x_kernel(const float* __restrict__ x, int n2) {
    int i = blockIdx.x * blockDim.x + threadIdx.x;
    if (i < n2) {
        float2 v = reinterpret_cast<const float2*>(x)[i];
        __nv_bfloat162 o;
        o.x = __float2bfloat16_rn(v.x);
        o.y = __float2bfloat16_rn(v.y);
        reinterpret_cast<__nv_bfloat162*>(g_hb16[0])[i] = o;
    }
}

__global__ void wconv_kernel(const float* __restrict__ Vw,
                             const float* __restrict__ Aw, int total) {
    int idx = blockIdx.x * blockDim.x + threadIdx.x;  // 3*2*16384
    if (idx >= total) return;
    int l = idx / (2 * DIMX * DIMX);
    int rem = idx - l * 2 * DIMX * DIMX;
    int phase = rem >> 14;
    int e = rem & 16383;
    const float* W = phase ? Aw : Vw;
    g_Wb16[idx] = __float2bfloat16_rn(W[l * DIMX * DIMX + e]);
}

__global__ void zero_cnt_kernel(int n) {
    int i = blockIdx.x * blockDim.x + threadIdx.x;
    if (i < n) g_cnt[i] = 0;
}

__global__ void hist_kernel(const int* __restrict__ dst, int e) {
    int i = blockIdx.x * blockDim.x + threadIdx.x;
    if (i < e) atomicAdd(&g_cnt[dst[i]], 1);
}

// phase 1: per-block scan of g_cnt (1024/block)
__global__ void scan1_kernel(int n) {
    __shared__ int s[1024];
    int i = blockIdx.x * 1024 + threadIdx.x;
    int v = (i < n) ? g_cnt[i] : 0;
    s[threadIdx.x] = v;
    __syncthreads();
    for (int off = 1; off < 1024; off <<= 1) {
        int t = (threadIdx.x >= off) ? s[threadIdx.x - off] : 0;
        __syncthreads();
        s[threadIdx.x] += t;
        __syncthreads();
    }
    if (i < n) g_off[i] = s[threadIdx.x] - v;   // block-local exclusive
    if (threadIdx.x == 1023) g_bsum[blockIdx.x] = s[1023];
}

// phase 2: scan the <=64 block partials (single block, 64 threads)
__global__ void scan2_kernel(int nb, int n) {
    __shared__ int s[64];
    int b = threadIdx.x;
    int v = (b < nb) ? g_bsum[b] : 0;
    s[b] = v;
    __syncthreads();
    for (int off = 1; off < 64; off <<= 1) {
        int t = (b >= off) ? s[b - off] : 0;
        __syncthreads();
        s[b] += t;
        __syncthreads();
    }
    if (b < nb) g_bsum[b] = s[b] - v;           // exclusive
    if (b == nb - 1) g_off[n] = s[b];           // total edge count
}

// phase 3: add block offsets; re-zero cnt for scatter
__global__ void scan3_kernel(int n) {
    int i = blockIdx.x * blockDim.x + threadIdx.x;
    if (i < n) {
        g_off[i] += g_bsum[i >> 10];
        g_cnt[i] = 0;
    }
}

__global__ void scatter_kernel(const int* __restrict__ src,
                               const int* __restrict__ dst, int e) {
    int i = blockIdx.x * blockDim.x + threadIdx.x;
    if (i < e) {
        int d = dst[i];
        int pos = g_off[d] + atomicAdd(&g_cnt[d], 1);
        g_srt[pos] = src[i];
    }
}

// ================= per-layer kernels =================

__global__ void zero_ro_kernel() { g_ro[threadIdx.x] = 0.0f; }

__global__ void readout_kernel(int insel, int n) {
    const __nv_bfloat16* __restrict__ h = g_hb16[insel];
    int j = threadIdx.x;  // 128 threads
    float s = 0.0f;
    for (int i = blockIdx.x; i < n; i += gridDim.x)
        s += __bfloat162float(h[i * DIMX + j]);
    atomicAdd(&g_ro[j], s);
}

__global__ void bias_kernel(const float* __restrict__ Vb,
                            const float* __restrict__ Ab,
                            const float* __restrict__ Rb,
                            const float* __restrict__ Rw, int l) {
    int j = threadIdx.x;  // 128 threads
    const float* r = Rw + (size_t)l * DIMX * DIMX + (size_t)j * DIMX;
    float acc = 0.0f;
#pragma unroll 4
    for (int k = 0; k < DIMX; k++) acc += g_ro[k] * r[k];
    g_bias[j] = Vb[l * DIMX + j] + Ab[l * DIMX + j] + Rb[l * DIMX + j] + acc;
}

// agg[i] = h[i] + sum_{e in csr(i)} h[srt[e]]   (bf16 in/out, fp32 accumulate)
__global__ void agg_kernel(int insel, int n) {
    const __nv_bfloat162* __restrict__ h =
        reinterpret_cast<const __nv_bfloat162*>(g_hb16[insel]);
    __nv_bfloat162* __restrict__ agg =
        reinterpret_cast<__nv_bfloat162*>(g_aggb16);
    int i = blockIdx.x;
    int j = threadIdx.x;  // 64 threads, 2 dims each
    int beg = g_off[i], end = g_off[i + 1];
    __nv_bfloat162 hv = h[i * 64 + j];
    float s0 = __bfloat162float(hv.x), s1 = __bfloat162float(hv.y);
    int e = beg;
    for (; e + 4 <= end; e += 4) {
        int i0 = g_srt[e + 0], i1 = g_srt[e + 1];
        int i2 = g_srt[e + 2], i3 = g_srt[e + 3];
        __nv_bfloat162 v0 = h[i0 * 64 + j];
        __nv_bfloat162 v1 = h[i1 * 64 + j];
        __nv_bfloat162 v2 = h[i2 * 64 + j];
        __nv_bfloat162 v3 = h[i3 * 64 + j];
        s0 += __bfloat162float(v0.x) + __bfloat162float(v1.x)
            + __bfloat162float(v2.x) + __bfloat162float(v3.x);
        s1 += __bfloat162float(v0.y) + __bfloat162float(v1.y)
            + __bfloat162float(v2.y) + __bfloat162float(v3.y);
    }
    for (; e < end; ++e) {
        __nv_bfloat162 v = h[g_srt[e] * 64 + j];
        s0 += __bfloat162float(v.x);
        s1 += __bfloat162float(v.y);
    }
    __nv_bfloat162 o;
    o.x = __float2bfloat16_rn(s0);
    o.y = __float2bfloat16_rn(s1);
    agg[i * 64 + j] = o;
}

// ====== HMMA bf16 GEMM: h_out = relu([h|agg] @ [Vw;Aw]^T + bias) ======
// block: 128(M) x 128(N), 2 K-phases of 128. 8 warps, each 64x32.
// smem tiles XOR-swizzled for conflict-free ldmatrix.

#define GS_A   0
#define GS_B   32768
#define GS_BIAS 65536
#define GEMM_SMEM (65536 + 512)

__global__ void __launch_bounds__(256, 2)
gemm_mma_kernel(int insel, int outsel, int l, int n) {
    extern __shared__ char smem[];
    __nv_bfloat16* As = (__nv_bfloat16*)(smem + GS_A);
    __nv_bfloat16* Bs = (__nv_bfloat16*)(smem + GS_B);
    float* sbias = (float*)(smem + GS_BIAS);
    const int tid = threadIdx.x;
    const int wid = tid >> 5, lane = tid & 31;
    const int bm = blockIdx.x * 128;
    const int wm = (wid & 1) * 64;    // warp m offset
    const int wn = (wid >> 1) * 32;   // warp n offset

    if (tid < 128) sbias[tid] = g_bias[tid];

    float acc[4][4][4];
#pragma unroll
    for (int a = 0; a < 4; a++)
#pragma unroll
        for (int b = 0; b < 4; b++)
#pragma unroll
            for (int c = 0; c < 4; c++) acc[a][b][c] = 0.0f;

    const uint32_t sA = smem_u32(As);
    const uint32_t sB = smem_u32(Bs);

#pragma unroll
    for (int phase = 0; phase < 2; phase++) {
        const __nv_bfloat16* __restrict__ A = phase ? g_aggb16 : g_hb16[insel];
        const __nv_bfloat16* __restrict__ W =
            g_Wb16 + (size_t)l * 32768 + phase * 16384;

        // fill tiles: 16B per thread-iter; chunk index XOR-swizzled by row&7
#pragma unroll
        for (int t = 0; t < 8; t++) {
            int idx = tid + t * 256;
            int row = idx >> 4;
            int c = idx & 15;
            uint32_t so = (uint32_t)(row * 256 + ((c ^ (row & 7)) << 4));
            int gm = bm + row;
            uint4 av = make_uint4(0, 0, 0, 0);
            if (gm < n) av = *(const uint4*)(A + (size_t)gm * DIMX + c * 8);
            *(uint4*)((char*)As + so) = av;
            *(uint4*)((char*)Bs + so) = *(const uint4*)(W + row * DIMX + c * 8);
        }
        __syncthreads();

#pragma unroll
        for (int ks = 0; ks < 8; ks++) {
            const int kc = ks * 2;  // 8-col chunk base for this k16 step
            uint32_t a[4][4], b[2][4];
#pragma unroll
            for (int mi = 0; mi < 4; mi++) {
                int row = wm + mi * 16 + (lane & 15);
                int c = kc + (lane >> 4);
                ldm_x4(a[mi], sA + row * 256 + ((c ^ (row & 7)) << 4));
            }
#pragma unroll
            for (int nj = 0; nj < 2; nj++) {
                int row = wn + nj * 16 + ((lane >> 4) << 3) + (lane & 7);
                int c = kc + ((lane >> 3) & 1);
                ldm_x4(b[nj], sB + row * 256 + ((c ^ (row & 7)) << 4));
            }
#pragma unroll
            for (int mi = 0; mi < 4; mi++) {
                mma_bf16(acc[mi][0], a[mi], &b[0][0]);
                mma_bf16(acc[mi][1], a[mi], &b[0][2]);
                mma_bf16(acc[mi][2], a[mi], &b[1][0]);
                mma_bf16(acc[mi][3], a[mi], &b[1][2]);
            }
        }
        __syncthreads();
    }

    // epilogue: bias + relu + bf16 store
    __nv_bfloat16* __restrict__ O = g_hb16[outsel];
    const int qr = lane >> 2;
    const int qc = (lane & 3) * 2;
#pragma unroll
    for (int mi = 0; mi < 4; mi++) {
        int r0 = bm + wm + mi * 16 + qr;
#pragma unroll
        for (int ni = 0; ni < 4; ni++) {
            int col = wn + ni * 8 + qc;
            float b0 = sbias[col], b1 = sbias[col + 1];
            if (r0 < n) {
                __nv_bfloat162 p;
                p.x = __float2bfloat16_rn(fmaxf(acc[mi][ni][0] + b0, 0.f));
                p.y = __float2bfloat16_rn(fmaxf(acc[mi][ni][1] + b1, 0.f));
                *(__nv_bfloat162*)(O + (size_t)r0 * DIMX + col) = p;
            }
            if (r0 + 8 < n) {
                __nv_bfloat162 p;
                p.x = __float2bfloat16_rn(fmaxf(acc[mi][ni][2] + b0, 0.f));
                p.y = __float2bfloat16_rn(fmaxf(acc[mi][ni][3] + b1, 0.f));
                *(__nv_bfloat162*)(O + (size_t)(r0 + 8) * DIMX + col) = p;
            }
        }
    }
}

// ================= output head =================

__global__ void out_kernel(int insel, const float* __restrict__ ow,
                           const float* __restrict__ ob,
                           float* __restrict__ out, int n) {
    const __nv_bfloat16* __restrict__ h = g_hb16[insel];
    int gw = (blockIdx.x * blockDim.x + threadIdx.x) >> 5;
    int lane = threadIdx.x & 31;
    if (gw >= n) return;
    const __nv_bfloat16* hr = h + (size_t)gw * DIMX;
    float a0 = 0.f, a1 = 0.f;
#pragma unroll
    for (int k = lane; k < DIMX; k += 32) {
        float v = __bfloat162float(hr[k]);
        a0 += v * ow[k];
        a1 += v * ow[DIMX + k];
    }
#pragma unroll
    for (int o = 16; o; o >>= 1) {
        a0 += __shfl_down_sync(0xffffffffu, a0, o);
        a1 += __shfl_down_sync(0xffffffffu, a1, o);
    }
    if (lane == 0) {
        out[gw * 2 + 0] = 1.0f / (1.0f + __expf(-(a0 + ob[0])));
        out[gw * 2 + 1] = 1.0f / (1.0f + __expf(-(a1 + ob[1])));
    }
}

// ================= launch =================

extern "C" void kernel_launch(void* const* d_in, const int* in_sizes, int n_in,
                              void* d_out, int out_size) {
    const float* x  = (const float*)d_in[0];
    const int* src  = (const int*)d_in[1];
    const int* dst  = (const int*)d_in[2];
    const float* Vw = (const float*)d_in[3];
    const float* Vb = (const float*)d_in[4];
    const float* Aw = (const float*)d_in[5];
    const float* Ab = (const float*)d_in[6];
    const float* Rw = (const float*)d_in[7];
    const float* Rb = (const float*)d_in[8];
    const float* ow = (const float*)d_in[9];
    const float* ob = (const float*)d_in[10];
    float* out = (float*)d_out;

    const int n = in_sizes[0] / DIMX;   // 50000
    const int e = in_sizes[1];          // 800000

    cudaFuncSetAttribute(gemm_mma_kernel,
                         cudaFuncAttributeMaxDynamicSharedMemorySize, GEMM_SMEM);

    // stage bf16 input + convert all layer weights
    int n2 = (n * DIMX) / 2;
    copy_x_kernel<<<(n2 + 255) / 256, 256>>>(x, n2);
    int wtot = 3 * 2 * DIMX * DIMX;
    wconv_kernel<<<(wtot + 255) / 256, 256>>>(Vw, Aw, wtot);

    // build CSR by dst (parallel scan)
    int nb = (n + 1023) / 1024;
    zero_cnt_kernel<<<(n + 255) / 256, 256>>>(n);
    hist_kernel<<<(e + 255) / 256, 256>>>(dst, e);
    scan1_kernel<<<nb, 1024>>>(n);
    scan2_kernel<<<1, 64>>>(nb, n);
    scan3_kernel<<<(n + 255) / 256, 256>>>(n);
    scatter_kernel<<<(e + 255) / 256, 256>>>(src, dst, e);

    for (int l = 0; l < 3; l++) {
        int insel = l & 1;       // 0,1,0
        int outsel = insel ^ 1;  // 1,0,1
        zero_ro_kernel<<<1, 128>>>();
        readout_kernel<<<512, 128>>>(insel, n);
        bias_kernel<<<1, 128>>>(Vb, Ab, Rb, Rw, l);
        agg_kernel<<<n, 64>>>(insel, n);
        gemm_mma_kernel<<<(n + 127) / 128, 256, GEMM_SMEM>>>(insel, outsel, l, n);
    }

    // final hidden state in g_hb16[1]
    out_kernel<<<(n + 7) / 8, 256>>>(1, ow, ob, out, n);
}

// round 6
// speedup vs baseline: 2.4137x; 1.1587x over previous
#include <cuda_runtime.h>
#include <cuda_bf16.h>
#include <cstdint>

#define NN 50000
#define DIMX 128
#define NE 800000

// ---- scratch (static __device__ globals; no runtime allocation) ----
__device__ __nv_bfloat16 g_hb16[2][NN * DIMX];   // ping-pong hidden states (bf16)
__device__ __nv_bfloat16 g_aggb16[NN * DIMX];    // aggregation (bf16)
__device__ __nv_bfloat16 g_Wb16[3 * 2 * DIMX * DIMX]; // [layer][phase V/A][n][k]
__device__ int   g_off[NN + 1];
__device__ int   g_cnt[NN];
__device__ int   g_srt[NE];
__device__ int   g_bsum[64];
__device__ float g_ro_all[4][DIMX];   // readout per layer (0 from x; l+1 from gemm l)

// ================= helpers =================

__device__ __forceinline__ uint32_t smem_u32(const void* p) {
    uint32_t a;
    asm("{ .reg .u64 t; cvta.to.shared.u64 t, %1; cvt.u32.u64 %0, t; }"
        : "=r"(a) : "l"(p));
    return a;
}

__device__ __forceinline__ void ldm_x4(uint32_t* r, uint32_t addr) {
    asm volatile("ldmatrix.sync.aligned.m8n8.x4.shared.b16 {%0,%1,%2,%3}, [%4];"
                 : "=r"(r[0]), "=r"(r[1]), "=r"(r[2]), "=r"(r[3]) : "r"(addr));
}

__device__ __forceinline__ void mma_bf16(float* c, const uint32_t* a,
                                         const uint32_t* b) {
    asm volatile(
        "mma.sync.aligned.m16n8k16.row.col.f32.bf16.bf16.f32 "
        "{%0,%1,%2,%3}, {%4,%5,%6,%7}, {%8,%9}, {%0,%1,%2,%3};"
        : "+f"(c[0]), "+f"(c[1]), "+f"(c[2]), "+f"(c[3])
        : "r"(a[0]), "r"(a[1]), "r"(a[2]), "r"(a[3]), "r"(b[0]), "r"(b[1]));
}

__device__ __forceinline__ void cp16(uint32_t dst, const void* src, int sz) {
    asm volatile("cp.async.cg.shared.global [%0], [%1], 16, %2;"
                 :: "r"(dst), "l"(src), "r"(sz) : "memory");
}
#define CP_COMMIT() asm volatile("cp.async.commit_group;" ::: "memory")
#define CP_WAIT(N)  asm volatile("cp.async.wait_group %0;" :: "n"(N) : "memory")

// unpack bf16x2 word into two fp32 adds
__device__ __forceinline__ void acc_bf2(float& a0, float& a1, uint32_t w) {
    a0 += __uint_as_float(w << 16);
    a1 += __uint_as_float(w & 0xffff0000u);
}

// pack two fp32 into one bf16x2 word (rn)
__device__ __forceinline__ uint32_t pack_bf2(float lo, float hi) {
    uint32_t r;
    asm("cvt.rn.bf16x2.f32 %0, %1, %2;" : "=r"(r) : "f"(hi), "f"(lo));
    return r;
}

// ================= setup (fused copy_x + wconv + zero cnt/ro) =================

__global__ void setup_kernel(const float* __restrict__ x,
                             const float* __restrict__ Vw,
                             const float* __restrict__ Aw, int n2, int n) {
    int i = blockIdx.x * blockDim.x + threadIdx.x;
    if (i < n2) {
        float2 v = reinterpret_cast<const float2*>(x)[i];
        __nv_bfloat162 o;
        o.x = __float2bfloat16_rn(v.x);
        o.y = __float2bfloat16_rn(v.y);
        reinterpret_cast<__nv_bfloat162*>(g_hb16[0])[i] = o;
    }
    if (i < 3 * 2 * DIMX * DIMX) {
        int l = i / (2 * DIMX * DIMX);
        int rem = i - l * 2 * DIMX * DIMX;
        int phase = rem >> 14;
        int e = rem & 16383;
        const float* W = phase ? Aw : Vw;
        g_Wb16[i] = __float2bfloat16_rn(W[l * DIMX * DIMX + e]);
    }
    if (i < n) g_cnt[i] = 0;
    if (i < 4 * DIMX) ((float*)g_ro_all)[i] = 0.0f;
}

// ================= CSR build =================

__global__ void hist_kernel(const int* __restrict__ dst, int e) {
    int i = blockIdx.x * blockDim.x + threadIdx.x;
    if (i < e) atomicAdd(&g_cnt[dst[i]], 1);
}

__global__ void scan1_kernel(int n) {
    __shared__ int s[1024];
    int i = blockIdx.x * 1024 + threadIdx.x;
    int v = (i < n) ? g_cnt[i] : 0;
    s[threadIdx.x] = v;
    __syncthreads();
    for (int off = 1; off < 1024; off <<= 1) {
        int t = (threadIdx.x >= off) ? s[threadIdx.x - off] : 0;
        __syncthreads();
        s[threadIdx.x] += t;
        __syncthreads();
    }
    if (i < n) g_off[i] = s[threadIdx.x] - v;
    if (threadIdx.x == 1023) g_bsum[blockIdx.x] = s[1023];
}

__global__ void scan2_kernel(int nb, int n) {
    __shared__ int s[64];
    int b = threadIdx.x;
    int v = (b < nb) ? g_bsum[b] : 0;
    s[b] = v;
    __syncthreads();
    for (int off = 1; off < 64; off <<= 1) {
        int t = (b >= off) ? s[b - off] : 0;
        __syncthreads();
        s[b] += t;
        __syncthreads();
    }
    if (b < nb) g_bsum[b] = s[b] - v;
    if (b == nb - 1) g_off[n] = s[b];
}

__global__ void scan3_kernel(int n) {
    int i = blockIdx.x * blockDim.x + threadIdx.x;
    if (i < n) {
        g_off[i] += g_bsum[i >> 10];
        g_cnt[i] = 0;
    }
}

__global__ void scatter_kernel(const int* __restrict__ src,
                               const int* __restrict__ dst, int e) {
    int i = blockIdx.x * blockDim.x + threadIdx.x;
    if (i < e) {
        int d = dst[i];
        int pos = g_off[d] + atomicAdd(&g_cnt[d], 1);
        g_srt[pos] = src[i];
    }
}

// ================= readout of layer-0 input =================

__global__ void readout0_kernel(int n) {
    const __nv_bfloat16* __restrict__ h = g_hb16[0];
    int j = threadIdx.x;  // 128
    float s = 0.0f;
    for (int i = blockIdx.x; i < n; i += gridDim.x)
        s += __bfloat162float(h[i * DIMX + j]);
    atomicAdd(&g_ro_all[0][j], s);
}

// ================= aggregation: warp per node, uint4 gathers =================
// agg[i] = h[i] + sum_{e in csr(i)} h[srt[e]]

__global__ void __launch_bounds__(256)
agg_kernel(int insel, int n) {
    int w = (blockIdx.x * blockDim.x + threadIdx.x) >> 5;
    if (w >= n) return;
    int lane = threadIdx.x & 31;
    int c = lane & 15;   // 16B chunk within 256B row
    int p = lane >> 4;   // edge parity
    const uint4* __restrict__ h4 =
        reinterpret_cast<const uint4*>(g_hb16[insel]);

    float a[8];
#pragma unroll
    for (int k = 0; k < 8; k++) a[k] = 0.0f;

    if (p == 0) {  // self row counted once
        uint4 v = h4[(size_t)w * 16 + c];
        acc_bf2(a[0], a[1], v.x);
        acc_bf2(a[2], a[3], v.y);
        acc_bf2(a[4], a[5], v.z);
        acc_bf2(a[6], a[7], v.w);
    }

    int beg = g_off[w], end = g_off[w + 1];
    int e = beg + p;
    for (; e + 2 < end; e += 4) {
        int r0 = g_srt[e];
        int r1 = g_srt[e + 2];
        uint4 v0 = h4[(size_t)r0 * 16 + c];
        uint4 v1 = h4[(size_t)r1 * 16 + c];
        acc_bf2(a[0], a[1], v0.x); acc_bf2(a[2], a[3], v0.y);
        acc_bf2(a[4], a[5], v0.z); acc_bf2(a[6], a[7], v0.w);
        acc_bf2(a[0], a[1], v1.x); acc_bf2(a[2], a[3], v1.y);
        acc_bf2(a[4], a[5], v1.z); acc_bf2(a[6], a[7], v1.w);
    }
    if (e < end) {
        int r0 = g_srt[e];
        uint4 v0 = h4[(size_t)r0 * 16 + c];
        acc_bf2(a[0], a[1], v0.x); acc_bf2(a[2], a[3], v0.y);
        acc_bf2(a[4], a[5], v0.z); acc_bf2(a[6], a[7], v0.w);
    }

    // combine the two edge-parity halves
#pragma unroll
    for (int k = 0; k < 8; k++)
        a[k] += __shfl_xor_sync(0xffffffffu, a[k], 16);

    if (p == 0) {
        uint4 o;
        o.x = pack_bf2(a[0], a[1]);
        o.y = pack_bf2(a[2], a[3]);
        o.z = pack_bf2(a[4], a[5]);
        o.w = pack_bf2(a[6], a[7]);
        reinterpret_cast<uint4*>(g_aggb16)[(size_t)w * 16 + c] = o;
    }
}

// ====== HMMA bf16 GEMM, cp.async pipelined, fused bias + next-layer readout ======
// h_out = relu([h|agg] @ [Vw;Aw]^T + bias); bias = Vb+Ab+Rb + ro@Rw^T.
// 4 K-chunks of 64; double-buffered (2 x 32KB).

#define GEMM_SMEM (65536 + 512)

__global__ void __launch_bounds__(256, 2)
gemm_mma_kernel(int insel, int outsel, int l, int n,
                const float* __restrict__ Vb, const float* __restrict__ Ab,
                const float* __restrict__ Rb, const float* __restrict__ Rw) {
    extern __shared__ char smem[];
    float* sbias = (float*)(smem + 65536);
    const int tid = threadIdx.x;
    const int wid = tid >> 5, lane = tid & 31;
    const int bm = blockIdx.x * 128;
    const int wm = (wid & 1) * 64;
    const int wn = (wid >> 1) * 32;
    const uint32_t sbase = smem_u32(smem);

    const __nv_bfloat16* __restrict__ A0 = g_hb16[insel];
    const __nv_bfloat16* __restrict__ A1 = g_aggb16;
    const __nv_bfloat16* __restrict__ W = g_Wb16 + (size_t)l * 32768;

    // ---- prefetch one K=64 chunk (A 16KB + B 16KB) into buffer buf ----
    auto prefetch = [&](int cs, int buf) {
        const __nv_bfloat16* __restrict__ Asrc = (cs < 2) ? A0 : A1;
        const __nv_bfloat16* __restrict__ Bsrc = W + ((cs >> 1) << 14);
        const int k0 = (cs & 1) * 64;
        const uint32_t sA = sbase + buf * 32768;
        const uint32_t sB = sA + 16384;
#pragma unroll
        for (int t = 0; t < 4; t++) {
            int idx = tid + t * 256;
            int row = idx >> 3, cc = idx & 7;
            uint32_t so = (uint32_t)(row * 128 + ((cc ^ (row & 7)) << 4));
            int gm = bm + row;
            int gmc = gm < n ? gm : 0;
            cp16(sA + so, Asrc + (size_t)gmc * DIMX + k0 + cc * 8,
                 gm < n ? 16 : 0);
            cp16(sB + so, Bsrc + row * DIMX + k0 + cc * 8, 16);
        }
        CP_COMMIT();
    };

    float acc[4][4][4];
#pragma unroll
    for (int a = 0; a < 4; a++)
#pragma unroll
        for (int b = 0; b < 4; b++)
#pragma unroll
            for (int c = 0; c < 4; c++) acc[a][b][c] = 0.0f;

    prefetch(0, 0);
    prefetch(1, 1);

    // bias while loads are in flight
    if (tid < 128) {
        float b = Vb[l * DIMX + tid] + Ab[l * DIMX + tid] + Rb[l * DIMX + tid];
        const float* __restrict__ ro = g_ro_all[l];
        const float* __restrict__ rw = Rw + (size_t)l * DIMX * DIMX
                                          + (size_t)tid * DIMX;
#pragma unroll 8
        for (int k = 0; k < DIMX; k++) b += ro[k] * rw[k];
        sbias[tid] = b;
    }

    auto compute = [&](int buf) {
        const uint32_t sA = sbase + buf * 32768;
        const uint32_t sB = sA + 16384;
#pragma unroll
        for (int ks = 0; ks < 4; ks++) {
            const int kc = ks * 2;
            uint32_t a[4][4], b[2][4];
#pragma unroll
            for (int mi = 0; mi < 4; mi++) {
                int row = wm + mi * 16 + (lane & 15);
                int c = kc + (lane >> 4);
                ldm_x4(a[mi], sA + row * 128 + ((c ^ (row & 7)) << 4));
            }
#pragma unroll
            for (int nj = 0; nj < 2; nj++) {
                int row = wn + nj * 16 + ((lane >> 4) << 3) + (lane & 7);
                int c = kc + ((lane >> 3) & 1);
                ldm_x4(b[nj], sB + row * 128 + ((c ^ (row & 7)) << 4));
            }
#pragma unroll
            for (int mi = 0; mi < 4; mi++) {
                mma_bf16(acc[mi][0], a[mi], &b[0][0]);
                mma_bf16(acc[mi][1], a[mi], &b[0][2]);
                mma_bf16(acc[mi][2], a[mi], &b[1][0]);
                mma_bf16(acc[mi][3], a[mi], &b[1][2]);
            }
        }
    };

    CP_WAIT(1); __syncthreads();
    compute(0);
    __syncthreads(); prefetch(2, 0);
    CP_WAIT(1); __syncthreads();
    compute(1);
    __syncthreads(); prefetch(3, 1);
    CP_WAIT(1); __syncthreads();
    compute(0);
    CP_WAIT(0); __syncthreads();
    compute(1);

    // ---- epilogue: bias + relu + store + next-layer readout partials ----
    __nv_bfloat16* __restrict__ O = g_hb16[outsel];
    float* __restrict__ ro_next = g_ro_all[l + 1];
    const int qr = lane >> 2;
    const int qc = (lane & 3) * 2;
    float colsum[4][2];
#pragma unroll
    for (int ni = 0; ni < 4; ni++) colsum[ni][0] = colsum[ni][1] = 0.0f;

#pragma unroll
    for (int mi = 0; mi < 4; mi++) {
        int r0 = bm + wm + mi * 16 + qr;
#pragma unroll
        for (int ni = 0; ni < 4; ni++) {
            int col = wn + ni * 8 + qc;
            float b0 = sbias[col], b1 = sbias[col + 1];
            float v0 = fmaxf(acc[mi][ni][0] + b0, 0.f);
            float v1 = fmaxf(acc[mi][ni][1] + b1, 0.f);
            float v2 = fmaxf(acc[mi][ni][2] + b0, 0.f);
            float v3 = fmaxf(acc[mi][ni][3] + b1, 0.f);
            if (r0 < n) {
                *(uint32_t*)(O + (size_t)r0 * DIMX + col) = pack_bf2(v0, v1);
                colsum[ni][0] += v0; colsum[ni][1] += v1;
            }
            if (r0 + 8 < n) {
                *(uint32_t*)(O + (size_t)(r0 + 8) * DIMX + col) = pack_bf2(v2, v3);
                colsum[ni][0] += v2; colsum[ni][1] += v3;
            }
        }
    }
    // reduce over the 8 row-lanes (qr bits of lane), then one RED per col
#pragma unroll
    for (int ni = 0; ni < 4; ni++)
#pragma unroll
        for (int j = 0; j < 2; j++) {
            float v = colsum[ni][j];
            v += __shfl_xor_sync(0xffffffffu, v, 4);
            v += __shfl_xor_sync(0xffffffffu, v, 8);
            v += __shfl_xor_sync(0xffffffffu, v, 16);
            if (lane < 4)
                atomicAdd(&ro_next[wn + ni * 8 + lane * 2 + j], v);
        }
}

// ================= output head =================

__global__ void out_kernel(int insel, const float* __restrict__ ow,
                           const float* __restrict__ ob,
                           float* __restrict__ out, int n) {
    const __nv_bfloat16* __restrict__ h = g_hb16[insel];
    int gw = (blockIdx.x * blockDim.x + threadIdx.x) >> 5;
    int lane = threadIdx.x & 31;
    if (gw >= n) return;
    const __nv_bfloat16* hr = h + (size_t)gw * DIMX;
    float a0 = 0.f, a1 = 0.f;
#pragma unroll
    for (int k = lane; k < DIMX; k += 32) {
        float v = __bfloat162float(hr[k]);
        a0 += v * ow[k];
        a1 += v * ow[DIMX + k];
    }
#pragma unroll
    for (int o = 16; o; o >>= 1) {
        a0 += __shfl_down_sync(0xffffffffu, a0, o);
        a1 += __shfl_down_sync(0xffffffffu, a1, o);
    }
    if (lane == 0) {
        out[gw * 2 + 0] = 1.0f / (1.0f + __expf(-(a0 + ob[0])));
        out[gw * 2 + 1] = 1.0f / (1.0f + __expf(-(a1 + ob[1])));
    }
}

// ================= launch =================

extern "C" void kernel_launch(void* const* d_in, const int* in_sizes, int n_in,
                              void* d_out, int out_size) {
    const float* x  = (const float*)d_in[0];
    const int* src  = (const int*)d_in[1];
    const int* dst  = (const int*)d_in[2];
    const float* Vw = (const float*)d_in[3];
    const float* Vb = (const float*)d_in[4];
    const float* Aw = (const float*)d_in[5];
    const float* Ab = (const float*)d_in[6];
    const float* Rw = (const float*)d_in[7];
    const float* Rb = (const float*)d_in[8];
    const float* ow = (const float*)d_in[9];
    const float* ob = (const float*)d_in[10];
    float* out = (float*)d_out;

    const int n = in_sizes[0] / DIMX;   // 50000
    const int e = in_sizes[1];          // 800000

    cudaFuncSetAttribute(gemm_mma_kernel,
                         cudaFuncAttributeMaxDynamicSharedMemorySize, GEMM_SMEM);

    int n2 = (n * DIMX) / 2;
    setup_kernel<<<(n2 + 255) / 256, 256>>>(x, Vw, Aw, n2, n);

    int nb = (n + 1023) / 1024;
    hist_kernel<<<(e + 255) / 256, 256>>>(dst, e);
    scan1_kernel<<<nb, 1024>>>(n);
    scan2_kernel<<<1, 64>>>(nb, n);
    scan3_kernel<<<(n + 255) / 256, 256>>>(n);
    scatter_kernel<<<(e + 255) / 256, 256>>>(src, dst, e);
    readout0_kernel<<<512, 128>>>(n);

    for (int l = 0; l < 3; l++) {
        int insel = l & 1;       // 0,1,0
        int outsel = insel ^ 1;  // 1,0,1
        agg_kernel<<<(n * 32 + 255) / 256, 256>>>(insel, n);
        gemm_mma_kernel<<<(n + 127) / 128, 256, GEMM_SMEM>>>(
            insel, outsel, l, n, Vb, Ab, Rb, Rw);
    }

    out_kernel<<<(n + 7) / 8, 256>>>(1, ow, ob, out, n);
}